// round 3
// baseline (speedup 1.0000x reference)
#include <cuda_runtime.h>

// PDELayer: 100 diffusion steps, 48x48, 8192 batches, frozen reflect boundary.
// Round 3: 1 warp = 1 batch. Thread tile 6 rows x 12 cols (36 f2) in registers.
// lane = trow*4 + tcol; trow 0..7 (6 rows each), tcol 0..3 (12 cols each).
// No shared memory, no __syncthreads. All halo via warp shuffle.
// Packed f32x2 math including horizontal sums via shifted-pair views.

#define NXY 48
#define NT  100

static __forceinline__ __device__ float2 f2add(float2 a, float2 b) {
    float2 d;
    asm("{\n\t.reg .b64 ra,rb,rd;\n\t"
        "mov.b64 ra,{%2,%3};\n\tmov.b64 rb,{%4,%5};\n\t"
        "add.rn.f32x2 rd, ra, rb;\n\t"
        "mov.b64 {%0,%1}, rd;\n\t}"
        : "=f"(d.x), "=f"(d.y)
        : "f"(a.x), "f"(a.y), "f"(b.x), "f"(b.y));
    return d;
}
static __forceinline__ __device__ float2 f2fma(float2 a, float2 b, float2 c) {
    float2 d;
    asm("{\n\t.reg .b64 ra,rb,rc,rd;\n\t"
        "mov.b64 ra,{%2,%3};\n\tmov.b64 rb,{%4,%5};\n\tmov.b64 rc,{%6,%7};\n\t"
        "fma.rn.f32x2 rd, ra, rb, rc;\n\t"
        "mov.b64 {%0,%1}, rd;\n\t}"
        : "=f"(d.x), "=f"(d.y)
        : "f"(a.x), "f"(a.y), "f"(b.x), "f"(b.y), "f"(c.x), "f"(c.y));
    return d;
}
static __forceinline__ __device__ float2 shfl_up2(float2 v, int delta) {
    float2 r;
    r.x = __shfl_up_sync(0xffffffffu, v.x, delta);
    r.y = __shfl_up_sync(0xffffffffu, v.y, delta);
    return r;
}
static __forceinline__ __device__ float2 shfl_dn2(float2 v, int delta) {
    float2 r;
    r.x = __shfl_down_sync(0xffffffffu, v.x, delta);
    r.y = __shfl_down_sync(0xffffffffu, v.y, delta);
    return r;
}

__global__ void __launch_bounds__(128)
pde_kernel(const float* __restrict__ u0,
           const float* __restrict__ aw1, const float* __restrict__ aw2,
           const float* __restrict__ aw3, const float* __restrict__ bw1,
           const float* __restrict__ bw2, const float* __restrict__ bw3,
           float* __restrict__ out)
{
    const int tid  = threadIdx.x;
    const int lane = tid & 31;
    const int warp = tid >> 5;
    const int tcol = lane & 3;         // 0..3  -> cols 12*tcol .. 12*tcol+11
    const int trow = lane >> 2;        // 0..7  -> rows 6*trow .. 6*trow+5
    const int b    = blockIdx.x * 4 + warp;

    const float2* g2 = (const float2*)(u0  + (size_t)b * (NXY * NXY));
    float2*       o2 = (float2*)      (out + (size_t)b * (NXY * NXY));

    // ---- coefficients ----
    const float TWO_PI = 6.283185307179586f;
    const float scale  = 1e-4f * 2304.0f;     // DT / DX^2
    const float inv47  = 1.0f / 47.0f;
    const float aa1 = fabsf(*aw1), aa2 = fabsf(*aw2), aa3 = fabsf(*aw3);
    const float bb1 = fabsf(*bw1), bb2 = fabsf(*bw2), bb3 = fabsf(*bw3);

    float2 a2[6];                      // alpha per local row (duplicated)
    #pragma unroll
    for (int r = 0; r < 6; r++) {
        float yv = (float)(6 * trow + r) * inv47;
        float al = 0.5f * scale * (aa1 + aa2 * sinf(TWO_PI * yv) + aa3 * cosf(TWO_PI * yv));
        a2[r] = make_float2(al, al);
    }
    float2 b2[6];                      // beta per column pair
    #pragma unroll
    for (int p = 0; p < 6; p++) {
        float x0 = (float)(12 * tcol + 2 * p)     * inv47;
        float x1 = (float)(12 * tcol + 2 * p + 1) * inv47;
        b2[p].x = scale * (bb1 + bb2 * cosf(TWO_PI * x0) + bb3 * sinf(TWO_PI * x0));
        b2[p].y = scale * (bb1 + bb2 * cosf(TWO_PI * x1) + bb3 * sinf(TWO_PI * x1));
    }
    const float2 m2 = make_float2(-2.0f, -2.0f);

    // ---- load 6x12 block ----
    float2 v[6][6];
    #pragma unroll
    for (int r = 0; r < 6; r++)
        #pragma unroll
        for (int p = 0; p < 6; p++)
            v[r][p] = g2[(6 * trow + r) * 24 + tcol * 6 + p];

    // ---- frozen reflected boundary (constants for all 100 steps) ----
    // top pad = u0 row 1 (trow0: local row 1); bottom pad = u0 row 46 (trow7: local row 4)
    float2 fv[6];
    #pragma unroll
    for (int p = 0; p < 6; p++) fv[p] = (trow == 0) ? v[1][p] : v[4][p];
    // left pad = u0 col 1 (tcol0: local col 1 = v[0].y); right pad = u0 col 46 (tcol3: local col 10 = v[5].x)
    float fh[6];
    #pragma unroll
    for (int r = 0; r < 6; r++) fh[r] = (tcol == 0) ? v[r][0].y : v[r][5].x;

    const bool isTop = (trow == 0), isBot = (trow == 7);
    const bool isL   = (tcol == 0), isR   = (tcol == 3);

    // ---- time loop ----
    #pragma unroll 1
    for (int t = 0; t < NT; t++) {
        // halos from OLD state
        float2 th[6], bh[6];
        #pragma unroll
        for (int p = 0; p < 6; p++) {
            float2 tu = shfl_up2(v[5][p], 4);
            float2 bd = shfl_dn2(v[0][p], 4);
            th[p] = isTop ? fv[p] : tu;
            bh[p] = isBot ? fv[p] : bd;
        }
        float lh[6], rh[6];
        #pragma unroll
        for (int r = 0; r < 6; r++) {
            float lu = __shfl_up_sync(0xffffffffu, v[r][5].y, 1);
            float rd = __shfl_down_sync(0xffffffffu, v[r][0].x, 1);
            lh[r] = isL ? fh[r] : lu;
            rh[r] = isR ? fh[r] : rd;
        }

        float2 prevold[6];
        #pragma unroll
        for (int p = 0; p < 6; p++) prevold[p] = th[p];

        #pragma unroll
        for (int r = 0; r < 6; r++) {
            // shifted views: L[p] = (cell[2p-1], cell[2p])
            float2 L[7];
            L[0] = make_float2(lh[r], v[r][0].x);
            #pragma unroll
            for (int p = 1; p < 6; p++)
                L[p] = make_float2(v[r][p - 1].y, v[r][p].x);
            L[6] = make_float2(v[r][5].y, rh[r]);

            #pragma unroll
            for (int p = 0; p < 6; p++) {
                float2 cur = v[r][p];
                float2 dn  = (r == 5) ? bh[p] : v[r + 1][p];
                float2 vs  = f2add(prevold[p], dn);       // up + dn
                vs = f2fma(m2, cur, vs);                  // up + dn - 2c
                float2 hs  = f2add(L[p], L[p + 1]);       // lf + rt
                hs = f2fma(m2, cur, hs);                  // lf + rt - 2c
                float2 tt  = f2fma(b2[p], hs, cur);       // c + b*hs
                prevold[p] = cur;
                v[r][p] = f2fma(a2[r], vs, tt);           // + a*vs
            }
        }
    }

    // ---- store ----
    #pragma unroll
    for (int r = 0; r < 6; r++)
        #pragma unroll
        for (int p = 0; p < 6; p++)
            o2[(6 * trow + r) * 24 + tcol * 6 + p] = v[r][p];
}

extern "C" void kernel_launch(void* const* d_in, const int* in_sizes, int n_in,
                              void* d_out, int out_size)
{
    const float* u0 = (const float*)d_in[0];
    int batches = in_sizes[0] / (NXY * NXY);
    int ctas = (batches + 3) / 4;
    pde_kernel<<<ctas, 128>>>(u0,
        (const float*)d_in[1], (const float*)d_in[2], (const float*)d_in[3],
        (const float*)d_in[4], (const float*)d_in[5], (const float*)d_in[6],
        (float*)d_out);
}

// round 5
// speedup vs baseline: 1.3481x; 1.3481x over previous
#include <cuda_runtime.h>

// PDELayer: 100 diffusion steps, 48x48, 8192 batches, frozen reflect boundary.
// Round 4: R2 layout (CTA=64 thr=1 batch, 6x6 tile/thread, seam smem + 1 barrier)
// with fused-coefficient update: res = a*(up+dn) + b*(lf+rt) + c0*cur,
// c0 = 1-2a-2b precomputed per (row,pair). 6 fma-pipe inst/pair (was 7).
// Horizontal sums stay SCALAR (packed shifted views cost parity MOVs).

#define NXY 48
#define NT  100

static __forceinline__ __device__ float2 f2add(float2 a, float2 b) {
    float2 d;
    asm("{\n\t.reg .b64 ra,rb,rd;\n\t"
        "mov.b64 ra,{%2,%3};\n\tmov.b64 rb,{%4,%5};\n\t"
        "add.rn.f32x2 rd, ra, rb;\n\t"
        "mov.b64 {%0,%1}, rd;\n\t}"
        : "=f"(d.x), "=f"(d.y)
        : "f"(a.x), "f"(a.y), "f"(b.x), "f"(b.y));
    return d;
}
static __forceinline__ __device__ float2 f2mul(float2 a, float2 b) {
    float2 d;
    asm("{\n\t.reg .b64 ra,rb,rd;\n\t"
        "mov.b64 ra,{%2,%3};\n\tmov.b64 rb,{%4,%5};\n\t"
        "mul.rn.f32x2 rd, ra, rb;\n\t"
        "mov.b64 {%0,%1}, rd;\n\t}"
        : "=f"(d.x), "=f"(d.y)
        : "f"(a.x), "f"(a.y), "f"(b.x), "f"(b.y));
    return d;
}
static __forceinline__ __device__ float2 f2fma(float2 a, float2 b, float2 c) {
    float2 d;
    asm("{\n\t.reg .b64 ra,rb,rc,rd;\n\t"
        "mov.b64 ra,{%2,%3};\n\tmov.b64 rb,{%4,%5};\n\tmov.b64 rc,{%6,%7};\n\t"
        "fma.rn.f32x2 rd, ra, rb, rc;\n\t"
        "mov.b64 {%0,%1}, rd;\n\t}"
        : "=f"(d.x), "=f"(d.y)
        : "f"(a.x), "f"(a.y), "f"(b.x), "f"(b.y), "f"(c.x), "f"(c.y));
    return d;
}
static __forceinline__ __device__ float2 shfl_up2(float2 v, int delta) {
    float2 r;
    r.x = __shfl_up_sync(0xffffffffu, v.x, delta);
    r.y = __shfl_up_sync(0xffffffffu, v.y, delta);
    return r;
}
static __forceinline__ __device__ float2 shfl_dn2(float2 v, int delta) {
    float2 r;
    r.x = __shfl_down_sync(0xffffffffu, v.x, delta);
    r.y = __shfl_down_sync(0xffffffffu, v.y, delta);
    return r;
}

__global__ void __launch_bounds__(64, 6)
pde_kernel(const float* __restrict__ u0,
           const float* __restrict__ aw1, const float* __restrict__ aw2,
           const float* __restrict__ aw3, const float* __restrict__ bw1,
           const float* __restrict__ bw2, const float* __restrict__ bw3,
           float* __restrict__ out)
{
    __shared__ float2 seamA[2][24];   // warp0 row 23 (bottom of gr==3)
    __shared__ float2 seamB[2][24];   // warp1 row 24 (top of gr==4)

    const int tid   = threadIdx.x;
    const int warp  = tid >> 5;
    const int lane  = tid & 31;
    const int tcol  = lane & 7;        // 0..7   -> cols 6*tcol..6*tcol+5
    const int trow  = lane >> 3;       // 0..3
    const int gr    = warp * 4 + trow; // 0..7   -> rows 6*gr..6*gr+5
    const int b     = blockIdx.x;

    const float2* g2 = (const float2*)(u0  + (size_t)b * (NXY * NXY));
    float2*       o2 = (float2*)      (out + (size_t)b * (NXY * NXY));

    // ---- coefficients ----
    const float TWO_PI = 6.283185307179586f;
    const float scale  = 1e-4f * 2304.0f;     // DT / DX^2
    const float inv47  = 1.0f / 47.0f;
    const float aa1 = fabsf(*aw1), aa2 = fabsf(*aw2), aa3 = fabsf(*aw3);
    const float bb1 = fabsf(*bw1), bb2 = fabsf(*bw2), bb3 = fabsf(*bw3);

    float2 a2[6];                     // alpha per local row (duplicated)
    #pragma unroll
    for (int r = 0; r < 6; r++) {
        float yv = (float)(6 * gr + r) * inv47;
        float al = 0.5f * scale * (aa1 + aa2 * sinf(TWO_PI * yv) + aa3 * cosf(TWO_PI * yv));
        a2[r] = make_float2(al, al);
    }
    float2 b2c[3];                    // beta per col pair
    #pragma unroll
    for (int p = 0; p < 3; p++) {
        float x0 = (float)(6 * tcol + 2 * p)     * inv47;
        float x1 = (float)(6 * tcol + 2 * p + 1) * inv47;
        b2c[p].x = scale * (bb1 + bb2 * cosf(TWO_PI * x0) + bb3 * sinf(TWO_PI * x0));
        b2c[p].y = scale * (bb1 + bb2 * cosf(TWO_PI * x1) + bb3 * sinf(TWO_PI * x1));
    }
    float2 c0[6][3];                  // 1 - 2a - 2b fused center coefficient
    #pragma unroll
    for (int r = 0; r < 6; r++)
        #pragma unroll
        for (int p = 0; p < 3; p++) {
            c0[r][p].x = 1.0f - 2.0f * a2[r].x - 2.0f * b2c[p].x;
            c0[r][p].y = 1.0f - 2.0f * a2[r].y - 2.0f * b2c[p].y;
        }

    // ---- load 6x6 block into registers ----
    float2 v[6][3];
    #pragma unroll
    for (int r = 0; r < 6; r++)
        #pragma unroll
        for (int p = 0; p < 3; p++)
            v[r][p] = g2[(6 * gr + r) * 24 + tcol * 3 + p];

    // ---- frozen reflected boundary = copies of own initial values ----
    float2 fv[3];
    #pragma unroll
    for (int p = 0; p < 3; p++) fv[p] = (gr == 0) ? v[1][p] : v[4][p];
    float fh[6];
    #pragma unroll
    for (int r = 0; r < 6; r++) fh[r] = (tcol == 0) ? v[r][0].y : v[r][2].x;

    const bool isTop = (gr == 0), isBot = (gr == 7);
    const bool sw0   = (gr == 3), sw1   = (gr == 4);   // seam writers/readers
    const bool isL   = (tcol == 0), isR = (tcol == 7);
    const int  sidx  = tcol * 3;

    // ---- time loop ----
    #pragma unroll 2
    for (int t = 0; t < NT; t++) {
        const int buf = t & 1;
        if (sw0) { seamA[buf][sidx] = v[5][0]; seamA[buf][sidx+1] = v[5][1]; seamA[buf][sidx+2] = v[5][2]; }
        if (sw1) { seamB[buf][sidx] = v[0][0]; seamB[buf][sidx+1] = v[0][1]; seamB[buf][sidx+2] = v[0][2]; }
        __syncthreads();

        // halos (OLD state)
        float2 th[3], bh[3];
        #pragma unroll
        for (int p = 0; p < 3; p++) {
            float2 tu = shfl_up2(v[5][p], 8);
            float2 bd = shfl_dn2(v[0][p], 8);
            th[p] = isTop ? fv[p] : (sw1 ? seamA[buf][sidx + p] : tu);
            bh[p] = isBot ? fv[p] : (sw0 ? seamB[buf][sidx + p] : bd);
        }
        float lh[6], rh[6];
        #pragma unroll
        for (int r = 0; r < 6; r++) {
            float lu = __shfl_up_sync(0xffffffffu, v[r][2].y, 1);
            float rd = __shfl_down_sync(0xffffffffu, v[r][0].x, 1);
            lh[r] = isL ? fh[r] : lu;
            rh[r] = isR ? fh[r] : rd;
        }

        // compute: res = a*(up+dn) + b*(lf+rt) + c0*cur
        float2 oldprev[3];
        #pragma unroll
        for (int p = 0; p < 3; p++) oldprev[p] = th[p];
        #pragma unroll
        for (int r = 0; r < 6; r++) {
            float x0 = v[r][0].x, x1 = v[r][0].y, x2 = v[r][1].x;
            float x3 = v[r][1].y, x4 = v[r][2].x, x5 = v[r][2].y;
            float s0 = lh[r] + x1, s1 = x0 + x2, s2 = x1 + x3;
            float s3 = x2 + x4,    s4 = x3 + x5, s5 = x4 + rh[r];

            #pragma unroll
            for (int p = 0; p < 3; p++) {
                float2 cur = v[r][p];
                float2 dn  = (r == 5) ? bh[p] : v[r + 1][p];
                float2 vs  = f2add(oldprev[p], dn);               // up + dn
                float2 hs  = (p == 0) ? make_float2(s0, s1)
                           : (p == 1) ? make_float2(s2, s3)
                                      : make_float2(s4, s5);
                float2 res = f2mul(c0[r][p], cur);                // c0*cur
                res = f2fma(b2c[p], hs, res);                     // + b*(lf+rt)
                res = f2fma(a2[r], vs, res);                      // + a*(up+dn)
                oldprev[p] = cur;
                v[r][p] = res;
            }
        }
    }

    // ---- store result ----
    #pragma unroll
    for (int r = 0; r < 6; r++)
        #pragma unroll
        for (int p = 0; p < 3; p++)
            o2[(6 * gr + r) * 24 + tcol * 3 + p] = v[r][p];
}

extern "C" void kernel_launch(void* const* d_in, const int* in_sizes, int n_in,
                              void* d_out, int out_size)
{
    const float* u0 = (const float*)d_in[0];
    int batches = in_sizes[0] / (NXY * NXY);
    pde_kernel<<<batches, 64>>>(u0,
        (const float*)d_in[1], (const float*)d_in[2], (const float*)d_in[3],
        (const float*)d_in[4], (const float*)d_in[5], (const float*)d_in[6],
        (float*)d_out);
}